// round 4
// baseline (speedup 1.0000x reference)
#include <cuda_runtime.h>
#include <cstdint>
#include <math.h>

// Problem constants (fixed by the dataset)
#define DIMK   2048              // feature dim D
#define PBANK  2048              // pseudo-ID classes per camera
#define CCAM   8                 // cameras
#define NTOT   (CCAM * PBANK)    // 16384 memory rows
#define KSEL   50                // hard-negative K
#define TEMP   0.07f
#define BMAX   256               // batch size

// ---------------- device scratch (no cudaMalloc allowed) ----------------
__device__ __align__(16) float g_xnorm[BMAX * DIMK];
__device__ __align__(16) float g_logits[BMAX * NTOT];   // 64 MB, zero-fill section
__device__ float g_ce[BMAX];
__device__ float g_lk[BMAX];

// ---------------- small utils ----------------
__device__ __forceinline__ float warp_sum(float v) {
#pragma unroll
    for (int o = 16; o; o >>= 1) v += __shfl_xor_sync(0xffffffffu, v, o);
    return v;
}
__device__ __forceinline__ float warp_max(float v) {
#pragma unroll
    for (int o = 16; o; o >>= 1) v = fmaxf(v, __shfl_xor_sync(0xffffffffu, v, o));
    return v;
}
// 256-thread block reductions; scr is 8-entry shared scratch.
__device__ __forceinline__ float block_sum(float v, float* scr) {
    v = warp_sum(v);
    __syncthreads();
    if ((threadIdx.x & 31) == 0) scr[threadIdx.x >> 5] = v;
    __syncthreads();
    float r = scr[0];
#pragma unroll
    for (int w = 1; w < 8; w++) r += scr[w];
    return r;
}
__device__ __forceinline__ float block_max(float v, float* scr) {
    v = warp_max(v);
    __syncthreads();
    if ((threadIdx.x & 31) == 0) scr[threadIdx.x >> 5] = v;
    __syncthreads();
    float r = scr[0];
#pragma unroll
    for (int w = 1; w < 8; w++) r = fmaxf(r, scr[w]);
    return r;
}

// float -> monotonically ordered unsigned key (ascending)
__device__ __forceinline__ unsigned fkey(float f) {
    unsigned u = __float_as_uint(f);
    return (u & 0x80000000u) ? ~u : (u | 0x80000000u);
}
__device__ __forceinline__ float funkey(unsigned k) {
    unsigned u = (k & 0x80000000u) ? (k ^ 0x80000000u) : ~k;
    return __uint_as_float(u);
}

__device__ __forceinline__ uint32_t f2tf32(float f) {
    uint32_t u;
    asm("cvt.rna.tf32.f32 %0, %1;" : "=r"(u) : "f"(f));
    return u;
}
__device__ __forceinline__ void mma_tf32(float c[4], const uint32_t a[4], const uint32_t b[2]) {
    asm volatile(
        "mma.sync.aligned.m16n8k8.row.col.f32.tf32.tf32.f32 "
        "{%0,%1,%2,%3}, {%4,%5,%6,%7}, {%8,%9}, {%0,%1,%2,%3};\n"
        : "+f"(c[0]), "+f"(c[1]), "+f"(c[2]), "+f"(c[3])
        : "r"(a[0]), "r"(a[1]), "r"(a[2]), "r"(a[3]), "r"(b[0]), "r"(b[1]));
}

// ---------------- kernel 1: row L2-normalize ----------------
__global__ __launch_bounds__(256) void normalize_kernel(const float* __restrict__ in) {
    __shared__ float scr[8];
    const int b = blockIdx.x;
    float s = 0.f;
    for (int i = threadIdx.x; i < DIMK; i += 256) {
        float v = in[b * DIMK + i];
        s += v * v;
    }
    s = block_sum(s, scr);
    const float inv = rsqrtf(s);
    for (int i = threadIdx.x; i < DIMK; i += 256)
        g_xnorm[b * DIMK + i] = in[b * DIMK + i] * inv;
}

// ---------------- kernel 2: tf32 GEMM  logits = x_norm @ tempV^T ----------------
// Block tile 128(M) x 128(N), K-step 32. 8 warps as 2x4; warp tile 64x32.
__global__ __launch_bounds__(256) void gemm_kernel(const float* __restrict__ Bv, int Brows) {
    __shared__ float As[128 * 33];
    __shared__ float Bs[128 * 33];
    const int bn = blockIdx.x, bm = blockIdx.y;
    const int tid = threadIdx.x, lane = tid & 31, warp = tid >> 5;
    const int wm = warp >> 2, wn = warp & 3;      // 2 x 4 warp grid
    const int g = lane >> 2, tg = lane & 3;       // groupID, thread-in-group

    float acc[4][4][4];
#pragma unroll
    for (int i = 0; i < 4; i++)
#pragma unroll
        for (int j = 0; j < 4; j++)
#pragma unroll
            for (int r = 0; r < 4; r++) acc[i][j][r] = 0.f;

    for (int k0 = 0; k0 < DIMK; k0 += 32) {
#pragma unroll
        for (int it = 0; it < 4; it++) {
            int idx = tid + it * 256;                  // 0..1023
            int r = idx >> 3, c4 = (idx & 7) << 2;     // row 0..127, col 0/4/.../28
            int ar = bm * 128 + r;
            float4 av;
            if (ar < Brows) av = *(const float4*)(g_xnorm + (size_t)ar * DIMK + k0 + c4);
            else            av = make_float4(0.f, 0.f, 0.f, 0.f);
            As[r * 33 + c4 + 0] = __uint_as_float(f2tf32(av.x));
            As[r * 33 + c4 + 1] = __uint_as_float(f2tf32(av.y));
            As[r * 33 + c4 + 2] = __uint_as_float(f2tf32(av.z));
            As[r * 33 + c4 + 3] = __uint_as_float(f2tf32(av.w));
            float4 bv = *(const float4*)(Bv + (size_t)(bn * 128 + r) * DIMK + k0 + c4);
            Bs[r * 33 + c4 + 0] = __uint_as_float(f2tf32(bv.x));
            Bs[r * 33 + c4 + 1] = __uint_as_float(f2tf32(bv.y));
            Bs[r * 33 + c4 + 2] = __uint_as_float(f2tf32(bv.z));
            Bs[r * 33 + c4 + 3] = __uint_as_float(f2tf32(bv.w));
        }
        __syncthreads();

#pragma unroll
        for (int ks = 0; ks < 4; ks++) {
            const int kb = ks * 8;
            uint32_t af[4][4];
            uint32_t bf[4][2];
#pragma unroll
            for (int i = 0; i < 4; i++) {
                int r0 = wm * 64 + i * 16 + g;
                af[i][0] = __float_as_uint(As[r0 * 33 + kb + tg]);
                af[i][1] = __float_as_uint(As[(r0 + 8) * 33 + kb + tg]);
                af[i][2] = __float_as_uint(As[r0 * 33 + kb + tg + 4]);
                af[i][3] = __float_as_uint(As[(r0 + 8) * 33 + kb + tg + 4]);
            }
#pragma unroll
            for (int j = 0; j < 4; j++) {
                int n0 = wn * 32 + j * 8 + g;
                bf[j][0] = __float_as_uint(Bs[n0 * 33 + kb + tg]);
                bf[j][1] = __float_as_uint(Bs[n0 * 33 + kb + tg + 4]);
            }
#pragma unroll
            for (int i = 0; i < 4; i++)
#pragma unroll
                for (int j = 0; j < 4; j++) mma_tf32(acc[i][j], af[i], bf[j]);
        }
        __syncthreads();
    }

    // epilogue
#pragma unroll
    for (int i = 0; i < 4; i++) {
#pragma unroll
        for (int j = 0; j < 4; j++) {
            int row = bm * 128 + wm * 64 + i * 16 + g;
            int col = bn * 128 + wn * 32 + j * 8 + 2 * tg;
            if (row < Brows)
                *(float2*)(g_logits + (size_t)row * NTOT + col) =
                    make_float2(acc[i][j][0], acc[i][j][1]);
            if (row + 8 < Brows)
                *(float2*)(g_logits + (size_t)(row + 8) * NTOT + col) =
                    make_float2(acc[i][j][2], acc[i][j][3]);
        }
    }
}

// ---------------- kernel 3: per-row losses (one block per sample) ----------------
__global__ __launch_bounds__(256) void rowloss_kernel(const int* __restrict__ labels,
                                                      const int* __restrict__ cams) {
    extern __shared__ float srow[];        // NTOT floats (64 KB)
    __shared__ float scr[8];
    __shared__ float s_ori[CCAM];
    __shared__ unsigned hist[256];
    __shared__ unsigned sh_prefix;
    __shared__ int sh_need;

    const int b = blockIdx.x, tid = threadIdx.x;
    const int cam = cams[b], label = labels[b];
    const float invT = 1.0f / TEMP;
    const float* row = g_logits + (size_t)b * NTOT;

    for (int i = tid; i < NTOT; i += 256) srow[i] = row[i];
    __syncthreads();

    // ---- intra-camera CE on own bank (unmasked) ----
    float mx = -1e30f;
    for (int i = tid; i < PBANK; i += 256) mx = fmaxf(mx, srow[cam * PBANK + i]);
    mx = block_max(mx, scr);
    float se = 0.f;
    for (int i = tid; i < PBANK; i += 256) se += expf((srow[cam * PBANK + i] - mx) * invT);
    se = block_sum(se, scr);
    const float ce = mx * invT + logf(se) - srow[cam * PBANK + label] * invT;

    // ---- save positives, then mask them ----
    if (tid < CCAM) s_ori[tid] = srow[tid * PBANK + label];
    __syncthreads();
    if (tid < CCAM) srow[tid * PBANK + label] = -10000.0f;
    __syncthreads();

    // ---- masked-row max, then fold in positives for a global stabilizer ----
    float m2 = -1e30f;
    for (int i = tid; i < NTOT; i += 256) m2 = fmaxf(m2, srow[i]);
    m2 = block_max(m2, scr);
    float M = m2;
#pragma unroll
    for (int c = 0; c < CCAM; c++) M = fmaxf(M, s_ori[c]);

    // ---- exact top-K threshold via 4-pass 256-bin radix select ----
    unsigned prefix = 0;
    int need = KSEL;
    for (int p = 0; p < 4; p++) {
        const int shift = 24 - 8 * p;
        hist[tid] = 0u;
        __syncthreads();
        for (int i = tid; i < NTOT; i += 256) {
            unsigned key = fkey(srow[i]);
            bool ok = (p == 0) || ((key >> (shift + 8)) == (prefix >> (shift + 8)));
            unsigned bal = __ballot_sync(0xffffffffu, ok);
            if (ok) {
                unsigned bin = (key >> shift) & 0xFFu;
                unsigned mm = __match_any_sync(bal, bin);
                if ((int)(tid & 31) == __ffs(mm) - 1)
                    atomicAdd(&hist[bin], (unsigned)__popc(mm));
            }
        }
        __syncthreads();
        if (tid == 0) {
            int cum = 0, bsel = 0;
            for (int bb = 255; bb >= 0; --bb) {
                int h = (int)hist[bb];
                if (cum + h >= need) { bsel = bb; break; }
                cum += h;
            }
            sh_need = need - cum;
            sh_prefix = prefix | ((unsigned)bsel << shift);
        }
        __syncthreads();
        prefix = sh_prefix;
        need = sh_need;
        __syncthreads();
    }
    const float tval = funkey(prefix);

    // ---- sum exp over the top-K negatives (strict-greater + `need` copies of t) ----
    float local = 0.f;
    for (int i = tid; i < NTOT; i += 256) {
        float v = srow[i];
        if (fkey(v) > prefix) local += expf((v - M) * invT);
    }
    local = block_sum(local, scr);

    if (tid == 0) {
        float ssel = local + (float)need * expf((tval - M) * invT);
        float sori = 0.f, osum = 0.f;
#pragma unroll
        for (int c = 0; c < CCAM; c++) {
            sori += expf((s_ori[c] - M) * invT);
            osum += s_ori[c];
        }
        float lse = M * invT + logf(ssel + sori);
        g_lk[b] = lse - osum * invT * (1.0f / (float)CCAM);
        g_ce[b] = ce;
    }
}

// ---------------- kernel 4: per-camera segment means (deterministic serial scans) ----------------
__global__ void final_kernel(const int* __restrict__ cams, float* __restrict__ out, int B) {
    __shared__ float s_i[CCAM], s_n[CCAM];
    const int c = threadIdx.x;
    if (c < CCAM) {
        float se = 0.f, sl = 0.f;
        int cnt = 0;
        for (int b = 0; b < B; ++b) {
            if (cams[b] == c) { se += g_ce[b]; sl += g_lk[b]; cnt++; }
        }
        s_i[c] = cnt ? se / (float)cnt : 0.f;
        s_n[c] = cnt ? sl / (float)cnt : 0.f;
    }
    __syncthreads();
    if (threadIdx.x == 0) {
        float a = 0.f, bsum = 0.f;
#pragma unroll
        for (int k = 0; k < CCAM; k++) { a += s_i[k]; bsum += s_n[k]; }
        out[0] = a;           // loss_intra
        out[1] = 0.5f * bsum; // loss_inter (LOSS_WEIGHT = 0.5)
    }
}

// ---------------- launch ----------------
extern "C" void kernel_launch(void* const* d_in, const int* in_sizes, int n_in,
                              void* d_out, int out_size) {
    const float* inputs = (const float*)d_in[0];
    const int*   labels = (const int*)d_in[1];
    const int*   cams   = (const int*)d_in[2];
    const float* tempV  = (const float*)d_in[3];
    const int B = in_sizes[1];  // labels element count

    normalize_kernel<<<B, 256>>>(inputs);

    dim3 grid(NTOT / 128, (B + 127) / 128);
    gemm_kernel<<<grid, 256>>>(tempV, B);

    cudaFuncSetAttribute(rowloss_kernel, cudaFuncAttributeMaxDynamicSharedMemorySize,
                         NTOT * (int)sizeof(float));
    rowloss_kernel<<<B, 256, NTOT * sizeof(float)>>>(labels, cams);

    final_kernel<<<1, 32>>>(cams, (float*)d_out, B);
}

// round 5
// speedup vs baseline: 2.2306x; 2.2306x over previous
#include <cuda_runtime.h>
#include <cuda_bf16.h>
#include <cstdint>
#include <math.h>

// Problem constants (fixed by the dataset)
#define DIMK   2048              // feature dim D
#define PBANK  2048              // pseudo-ID classes per camera
#define CCAM   8                 // cameras
#define NTOT   (CCAM * PBANK)    // 16384 memory rows
#define KSEL   50                // hard-negative K
#define TEMP   0.07f
#define BMAX   256               // batch size
#define CONVB  1792              // converter blocks in prep kernel

// ---------------- device scratch (no cudaMalloc allowed) ----------------
__device__ __align__(16) __nv_bfloat16 g_xb[BMAX * DIMK];    // normalized x, bf16
__device__ __align__(16) __nv_bfloat16 g_vb[NTOT * DIMK];    // tempV, bf16 (64 MB)
__device__ __align__(16) float g_logits[BMAX * NTOT];        // 16 MB
__device__ float g_ce[BMAX];
__device__ float g_lk[BMAX];

// ---------------- small utils ----------------
__device__ __forceinline__ float warp_sum(float v) {
#pragma unroll
    for (int o = 16; o; o >>= 1) v += __shfl_xor_sync(0xffffffffu, v, o);
    return v;
}
__device__ __forceinline__ float warp_max(float v) {
#pragma unroll
    for (int o = 16; o; o >>= 1) v = fmaxf(v, __shfl_xor_sync(0xffffffffu, v, o));
    return v;
}
__device__ __forceinline__ float block_sum(float v, float* scr) {
    v = warp_sum(v);
    __syncthreads();
    if ((threadIdx.x & 31) == 0) scr[threadIdx.x >> 5] = v;
    __syncthreads();
    float r = scr[0];
#pragma unroll
    for (int w = 1; w < 8; w++) r += scr[w];
    return r;
}
__device__ __forceinline__ float block_max(float v, float* scr) {
    v = warp_max(v);
    __syncthreads();
    if ((threadIdx.x & 31) == 0) scr[threadIdx.x >> 5] = v;
    __syncthreads();
    float r = scr[0];
#pragma unroll
    for (int w = 1; w < 8; w++) r = fmaxf(r, scr[w]);
    return r;
}

// float -> monotonically ordered unsigned key (ascending)
__device__ __forceinline__ unsigned fkey(float f) {
    unsigned u = __float_as_uint(f);
    return (u & 0x80000000u) ? ~u : (u | 0x80000000u);
}
__device__ __forceinline__ float funkey(unsigned k) {
    unsigned u = (k & 0x80000000u) ? (k ^ 0x80000000u) : ~k;
    return __uint_as_float(u);
}

// ---------------- cp.async helpers ----------------
__device__ __forceinline__ void cp_async16(uint32_t smem_addr, const void* gptr) {
    asm volatile("cp.async.cg.shared.global [%0], [%1], 16;\n"
                 :: "r"(smem_addr), "l"(gptr));
}
__device__ __forceinline__ void cp_commit() {
    asm volatile("cp.async.commit_group;\n" ::);
}
__device__ __forceinline__ void cp_wait1() {
    asm volatile("cp.async.wait_group 1;\n" ::);
}
__device__ __forceinline__ void cp_wait0() {
    asm volatile("cp.async.wait_group 0;\n" ::);
}

__device__ __forceinline__ void mma_bf16(float c[4], const uint32_t a[4], const uint32_t b[2]) {
    asm volatile(
        "mma.sync.aligned.m16n8k16.row.col.f32.bf16.bf16.f32 "
        "{%0,%1,%2,%3}, {%4,%5,%6,%7}, {%8,%9}, {%0,%1,%2,%3};\n"
        : "+f"(c[0]), "+f"(c[1]), "+f"(c[2]), "+f"(c[3])
        : "r"(a[0]), "r"(a[1]), "r"(a[2]), "r"(a[3]), "r"(b[0]), "r"(b[1]));
}

// ---------------- kernel 1: prep = row L2-normalize (bf16 out) + tempV fp32->bf16 ----------------
__global__ __launch_bounds__(256) void prep_kernel(const float* __restrict__ in,
                                                   const float* __restrict__ tv, int B) {
    __shared__ float scr[8];
    const int bid = blockIdx.x;
    if (bid < B) {
        const float4* row = (const float4*)(in + (size_t)bid * DIMK);
        float s = 0.f;
        for (int i = threadIdx.x; i < DIMK / 4; i += 256) {
            float4 a = row[i];
            s += a.x * a.x + a.y * a.y + a.z * a.z + a.w * a.w;
        }
        s = block_sum(s, scr);
        const float inv = rsqrtf(s);
        for (int i = threadIdx.x; i < DIMK / 4; i += 256) {
            float4 a = row[i];
            __nv_bfloat162 p0 = __floats2bfloat162_rn(a.x * inv, a.y * inv);
            __nv_bfloat162 p1 = __floats2bfloat162_rn(a.z * inv, a.w * inv);
            uint2 o;
            o.x = *(unsigned*)&p0; o.y = *(unsigned*)&p1;
            *(uint2*)(g_xb + (size_t)bid * DIMK + (size_t)i * 4) = o;
        }
    } else {
        const int cb = bid - B;
        const float4* src = (const float4*)tv;
        const long total = (long)NTOT * DIMK / 4;   // float4 count
        for (long i = (long)cb * 256 + threadIdx.x; i < total; i += (long)CONVB * 256) {
            float4 a = src[i];
            __nv_bfloat162 p0 = __floats2bfloat162_rn(a.x, a.y);
            __nv_bfloat162 p1 = __floats2bfloat162_rn(a.z, a.w);
            uint2 o;
            o.x = *(unsigned*)&p0; o.y = *(unsigned*)&p1;
            ((uint2*)g_vb)[i] = o;
        }
    }
}

// ---------------- kernel 2: bf16 GEMM  logits = x @ tempV^T ----------------
// Block tile 128(M) x 128(N), K-step 32 halves, 3-stage cp.async pipeline.
// SMEM row = 16 data uints (32 bf16) + 4 pad = 20 uints (80B -> 16B-aligned, conflict-free frags).
#define AROW_U  20
#define STAGE_U (128 * AROW_U)       // uints per matrix per stage
#define NKSTEP  (DIMK / 32)          // 64

__device__ __forceinline__ void gemm_load_stage(uint32_t* sm, int stage, int bm, int bn,
                                                int k0, int Brows, int tid) {
    uint32_t* As = sm + stage * 2 * STAGE_U;
    uint32_t* Bs = As + STAGE_U;
#pragma unroll
    for (int it = 0; it < 2; it++) {
        int idx = tid + it * 256;          // 0..511
        int r = idx >> 2, seg = idx & 3;   // row, 16B segment
        int ar = bm * 128 + r;
        if (ar >= Brows) ar = Brows - 1;   // clamp; rows >= Brows never stored
        const __nv_bfloat16* gp = g_xb + (size_t)ar * DIMK + k0 + seg * 8;
        cp_async16((uint32_t)__cvta_generic_to_shared(As + r * AROW_U + seg * 4), gp);
    }
#pragma unroll
    for (int it = 0; it < 2; it++) {
        int idx = tid + it * 256;
        int r = idx >> 2, seg = idx & 3;
        const __nv_bfloat16* gp = g_vb + (size_t)(bn * 128 + r) * DIMK + k0 + seg * 8;
        cp_async16((uint32_t)__cvta_generic_to_shared(Bs + r * AROW_U + seg * 4), gp);
    }
    cp_commit();
}

__global__ __launch_bounds__(256) void gemm_bf16(int Brows) {
    extern __shared__ uint32_t sm[];
    const int bn = blockIdx.x, bm = blockIdx.y;
    const int tid = threadIdx.x, lane = tid & 31, warp = tid >> 5;
    const int wm = warp >> 2, wn = warp & 3;   // 2 x 4 warp grid, warp tile 64x32
    const int g = lane >> 2, tg = lane & 3;

    float acc[4][4][4];
#pragma unroll
    for (int i = 0; i < 4; i++)
#pragma unroll
        for (int j = 0; j < 4; j++)
#pragma unroll
            for (int r = 0; r < 4; r++) acc[i][j][r] = 0.f;

    gemm_load_stage(sm, 0, bm, bn, 0, Brows, tid);
    gemm_load_stage(sm, 1, bm, bn, 32, Brows, tid);

    for (int kt = 0; kt < NKSTEP; kt++) {
        if (kt >= NKSTEP - 2) cp_wait0(); else cp_wait1();
        __syncthreads();

        const uint32_t* As = sm + (kt % 3) * 2 * STAGE_U;
        const uint32_t* Bs = As + STAGE_U;

#pragma unroll
        for (int ks = 0; ks < 2; ks++) {
            const int kb = ks * 8;   // uint offset of this k16 sub-step
            uint32_t af[4][4];
            uint32_t bf[4][2];
#pragma unroll
            for (int i = 0; i < 4; i++) {
                int r0 = wm * 64 + i * 16 + g;
                af[i][0] = As[r0 * AROW_U + kb + tg];
                af[i][1] = As[(r0 + 8) * AROW_U + kb + tg];
                af[i][2] = As[r0 * AROW_U + kb + tg + 4];
                af[i][3] = As[(r0 + 8) * AROW_U + kb + tg + 4];
            }
#pragma unroll
            for (int j = 0; j < 4; j++) {
                int n0 = wn * 32 + j * 8 + g;
                bf[j][0] = Bs[n0 * AROW_U + kb + tg];
                bf[j][1] = Bs[n0 * AROW_U + kb + tg + 4];
            }
#pragma unroll
            for (int i = 0; i < 4; i++)
#pragma unroll
                for (int j = 0; j < 4; j++) mma_bf16(acc[i][j], af[i], bf[j]);
        }

        if (kt + 2 < NKSTEP)
            gemm_load_stage(sm, (kt + 2) % 3, bm, bn, (kt + 2) * 32, Brows, tid);
    }

    // epilogue: c0,c1 = (row g, cols 2tg,2tg+1); c2,c3 = row g+8
#pragma unroll
    for (int i = 0; i < 4; i++) {
#pragma unroll
        for (int j = 0; j < 4; j++) {
            int row = bm * 128 + wm * 64 + i * 16 + g;
            int col = bn * 128 + wn * 32 + j * 8 + 2 * tg;
            if (row < Brows)
                *(float2*)(g_logits + (size_t)row * NTOT + col) =
                    make_float2(acc[i][j][0], acc[i][j][1]);
            if (row + 8 < Brows)
                *(float2*)(g_logits + (size_t)(row + 8) * NTOT + col) =
                    make_float2(acc[i][j][2], acc[i][j][3]);
        }
    }
}

// ---------------- kernel 3: per-row losses (one block per sample) ----------------
__global__ __launch_bounds__(256) void rowloss_kernel(const int* __restrict__ labels,
                                                      const int* __restrict__ cams) {
    extern __shared__ float srow[];        // NTOT floats (64 KB)
    __shared__ float scr[8];
    __shared__ float s_ori[CCAM];
    __shared__ unsigned hist[256];
    __shared__ unsigned sh_prefix;
    __shared__ int sh_need;

    const int b = blockIdx.x, tid = threadIdx.x;
    const int cam = cams[b], label = labels[b];
    const float invT = 1.0f / TEMP;
    const float* row = g_logits + (size_t)b * NTOT;

    for (int i = tid; i < NTOT; i += 256) srow[i] = row[i];
    __syncthreads();

    // ---- intra-camera CE on own bank (unmasked) ----
    float mx = -1e30f;
    for (int i = tid; i < PBANK; i += 256) mx = fmaxf(mx, srow[cam * PBANK + i]);
    mx = block_max(mx, scr);
    float se = 0.f;
    for (int i = tid; i < PBANK; i += 256) se += expf((srow[cam * PBANK + i] - mx) * invT);
    se = block_sum(se, scr);
    const float ce = mx * invT + logf(se) - srow[cam * PBANK + label] * invT;

    // ---- save positives, then mask them ----
    if (tid < CCAM) s_ori[tid] = srow[tid * PBANK + label];
    __syncthreads();
    if (tid < CCAM) srow[tid * PBANK + label] = -10000.0f;
    __syncthreads();

    // ---- masked-row max + positives -> global stabilizer ----
    float m2 = -1e30f;
    for (int i = tid; i < NTOT; i += 256) m2 = fmaxf(m2, srow[i]);
    m2 = block_max(m2, scr);
    float M = m2;
#pragma unroll
    for (int c = 0; c < CCAM; c++) M = fmaxf(M, s_ori[c]);

    // ---- exact top-K threshold via 4-pass 256-bin radix select ----
    unsigned prefix = 0;
    int need = KSEL;
    for (int p = 0; p < 4; p++) {
        const int shift = 24 - 8 * p;
        hist[tid] = 0u;
        __syncthreads();
        for (int i = tid; i < NTOT; i += 256) {
            unsigned key = fkey(srow[i]);
            bool ok = (p == 0) || ((key >> (shift + 8)) == (prefix >> (shift + 8)));
            unsigned bal = __ballot_sync(0xffffffffu, ok);
            if (ok) {
                unsigned bin = (key >> shift) & 0xFFu;
                unsigned mm = __match_any_sync(bal, bin);
                if ((int)(tid & 31) == __ffs(mm) - 1)
                    atomicAdd(&hist[bin], (unsigned)__popc(mm));
            }
        }
        __syncthreads();
        if (tid == 0) {
            int cum = 0, bsel = 0;
            for (int bb = 255; bb >= 0; --bb) {
                int h = (int)hist[bb];
                if (cum + h >= need) { bsel = bb; break; }
                cum += h;
            }
            sh_need = need - cum;
            sh_prefix = prefix | ((unsigned)bsel << shift);
        }
        __syncthreads();
        prefix = sh_prefix;
        need = sh_need;
        __syncthreads();
    }
    const float tval = funkey(prefix);

    // ---- sum exp over top-K negatives (strict-greater + `need` copies of threshold) ----
    float local = 0.f;
    for (int i = tid; i < NTOT; i += 256) {
        float v = srow[i];
        if (fkey(v) > prefix) local += expf((v - M) * invT);
    }
    local = block_sum(local, scr);

    if (tid == 0) {
        float ssel = local + (float)need * expf((tval - M) * invT);
        float sori = 0.f, osum = 0.f;
#pragma unroll
        for (int c = 0; c < CCAM; c++) {
            sori += expf((s_ori[c] - M) * invT);
            osum += s_ori[c];
        }
        float lse = M * invT + logf(ssel + sori);
        g_lk[b] = lse - osum * invT * (1.0f / (float)CCAM);
        g_ce[b] = ce;
    }
}

// ---------------- kernel 4: per-camera means, warp-per-camera, deterministic ----------------
__global__ __launch_bounds__(256) void final_kernel(const int* __restrict__ cams,
                                                    float* __restrict__ out, int B) {
    __shared__ float s_i[CCAM], s_n[CCAM];
    const int w = threadIdx.x >> 5;   // camera id (8 warps = 8 cams)
    const int l = threadIdx.x & 31;
    float se = 0.f, sl = 0.f, cn = 0.f;
    for (int b = l; b < B; b += 32) {
        if (cams[b] == w) { se += g_ce[b]; sl += g_lk[b]; cn += 1.f; }
    }
    se = warp_sum(se);
    sl = warp_sum(sl);
    cn = warp_sum(cn);
    if (l == 0) {
        s_i[w] = (cn > 0.f) ? se / cn : 0.f;
        s_n[w] = (cn > 0.f) ? sl / cn : 0.f;
    }
    __syncthreads();
    if (threadIdx.x == 0) {
        float a = 0.f, bsum = 0.f;
#pragma unroll
        for (int k = 0; k < CCAM; k++) { a += s_i[k]; bsum += s_n[k]; }
        out[0] = a;           // loss_intra
        out[1] = 0.5f * bsum; // loss_inter (LOSS_WEIGHT = 0.5)
    }
}

// ---------------- launch ----------------
extern "C" void kernel_launch(void* const* d_in, const int* in_sizes, int n_in,
                              void* d_out, int out_size) {
    const float* inputs = (const float*)d_in[0];
    const int*   labels = (const int*)d_in[1];
    const int*   cams   = (const int*)d_in[2];
    const float* tempV  = (const float*)d_in[3];
    const int B = in_sizes[1];  // labels element count

    prep_kernel<<<B + CONVB, 256>>>(inputs, tempV, B);

    const int gemm_smem = 3 * 2 * STAGE_U * (int)sizeof(uint32_t);   // 61440 B
    cudaFuncSetAttribute(gemm_bf16, cudaFuncAttributeMaxDynamicSharedMemorySize, gemm_smem);
    dim3 grid(NTOT / 128, (B + 127) / 128);
    gemm_bf16<<<grid, 256, gemm_smem>>>(B);

    cudaFuncSetAttribute(rowloss_kernel, cudaFuncAttributeMaxDynamicSharedMemorySize,
                         NTOT * (int)sizeof(float));
    rowloss_kernel<<<B, 256, NTOT * sizeof(float)>>>(labels, cams);

    final_kernel<<<1, 256>>>(cams, (float*)d_out, B);
}

// round 7
// speedup vs baseline: 2.5993x; 1.1653x over previous
#include <cuda_runtime.h>
#include <cuda_bf16.h>
#include <cstdint>
#include <math.h>

// Problem constants (fixed by the dataset)
#define DIMK   2048              // feature dim D
#define PBANK  2048              // pseudo-ID classes per camera
#define CCAM   8                 // cameras
#define NTOT   (CCAM * PBANK)    // 16384 memory rows
#define KSEL   50                // hard-negative K
#define TEMP   0.07f
#define BMAX   256               // batch size

// ---------------- device scratch (no cudaMalloc allowed) ----------------
__device__ __align__(16) __nv_bfloat16 g_xb[BMAX * DIMK];    // normalized x, bf16 (1 MB)
__device__ __align__(16) float g_logits[BMAX * NTOT];        // 16 MB
__device__ float g_ce[BMAX];
__device__ float g_lk[BMAX];

// ---------------- small utils ----------------
__device__ __forceinline__ float warp_sum(float v) {
#pragma unroll
    for (int o = 16; o; o >>= 1) v += __shfl_xor_sync(0xffffffffu, v, o);
    return v;
}
__device__ __forceinline__ float warp_max(float v) {
#pragma unroll
    for (int o = 16; o; o >>= 1) v = fmaxf(v, __shfl_xor_sync(0xffffffffu, v, o));
    return v;
}
__device__ __forceinline__ float block_sum(float v, float* scr) {
    v = warp_sum(v);
    __syncthreads();
    if ((threadIdx.x & 31) == 0) scr[threadIdx.x >> 5] = v;
    __syncthreads();
    float r = scr[0];
#pragma unroll
    for (int w = 1; w < 8; w++) r += scr[w];
    return r;
}
__device__ __forceinline__ float block_max(float v, float* scr) {
    v = warp_max(v);
    __syncthreads();
    if ((threadIdx.x & 31) == 0) scr[threadIdx.x >> 5] = v;
    __syncthreads();
    float r = scr[0];
#pragma unroll
    for (int w = 1; w < 8; w++) r = fmaxf(r, scr[w]);
    return r;
}
__device__ __forceinline__ unsigned fkey(float f) {
    unsigned u = __float_as_uint(f);
    return (u & 0x80000000u) ? ~u : (u | 0x80000000u);
}
__device__ __forceinline__ float funkey(unsigned k) {
    unsigned u = (k & 0x80000000u) ? (k ^ 0x80000000u) : ~k;
    return __uint_as_float(u);
}

// ---------------- cp.async helpers ----------------
__device__ __forceinline__ void cp_async16(uint32_t smem_addr, const void* gptr) {
    asm volatile("cp.async.cg.shared.global [%0], [%1], 16;\n"
                 :: "r"(smem_addr), "l"(gptr));
}
__device__ __forceinline__ void cp_commit() { asm volatile("cp.async.commit_group;\n" ::); }
__device__ __forceinline__ void cp_wait1()  { asm volatile("cp.async.wait_group 1;\n" ::); }
__device__ __forceinline__ void cp_wait0()  { asm volatile("cp.async.wait_group 0;\n" ::); }

__device__ __forceinline__ void mma_bf16(float c[4], const uint32_t a[4], const uint32_t b[2]) {
    asm volatile(
        "mma.sync.aligned.m16n8k16.row.col.f32.bf16.bf16.f32 "
        "{%0,%1,%2,%3}, {%4,%5,%6,%7}, {%8,%9}, {%0,%1,%2,%3};\n"
        : "+f"(c[0]), "+f"(c[1]), "+f"(c[2]), "+f"(c[3])
        : "r"(a[0]), "r"(a[1]), "r"(a[2]), "r"(a[3]), "r"(b[0]), "r"(b[1]));
}
__device__ __forceinline__ uint32_t cvt_bf16x2(float lo, float hi) {
    __nv_bfloat162 p = __floats2bfloat162_rn(lo, hi);
    return *(unsigned*)&p;
}

// ---------------- kernel 1: row L2-normalize -> bf16 (tiny now) ----------------
__global__ __launch_bounds__(256) void prep_kernel(const float* __restrict__ in) {
    __shared__ float scr[8];
    const int b = blockIdx.x;
    const float4* row = (const float4*)(in + (size_t)b * DIMK);
    float s = 0.f;
    for (int i = threadIdx.x; i < DIMK / 4; i += 256) {
        float4 a = row[i];
        s += a.x * a.x + a.y * a.y + a.z * a.z + a.w * a.w;
    }
    s = block_sum(s, scr);
    const float inv = rsqrtf(s);
    for (int i = threadIdx.x; i < DIMK / 4; i += 256) {
        float4 a = row[i];
        uint2 o;
        o.x = cvt_bf16x2(a.x * inv, a.y * inv);
        o.y = cvt_bf16x2(a.z * inv, a.w * inv);
        *(uint2*)(g_xb + (size_t)b * DIMK + (size_t)i * 4) = o;
    }
}

// ---------------- kernel 2: bf16 GEMM, B streamed as fp32 + in-register convert ----------------
// Block tile 128(M) x 128(N), K-step 32, 3-stage cp.async pipeline.
// A (bf16): row = 16 data uints + 4 pad = 20 uints (frag LDS.32 conflict-free).
// B (fp32): row = 32 data floats + 8 pad = 40 floats (frag LDS.64: bank 8g+2tg, conflict-free phases).
#define AROW_U  20
#define BROW_F  40
#define A_STAGE_U (128 * AROW_U)     // 2560 uints = 10240 B
#define B_STAGE_F (128 * BROW_F)     // 5120 floats = 20480 B
#define STAGE_U   (A_STAGE_U + B_STAGE_F)   // in 4B words: 7680 (30720 B)
#define NKSTEP  (DIMK / 32)          // 64
#define GSMEM   (3 * STAGE_U * 4)    // 92160 B

__device__ __forceinline__ void gemm_load_stage(uint32_t smb, int stage, int bm, int bn,
                                                int k0, const float* __restrict__ Bv,
                                                int tid) {
    const uint32_t a_base = smb + stage * (STAGE_U * 4);
    const uint32_t b_base = a_base + A_STAGE_U * 4;
    // A: 512 x 16B chunks
#pragma unroll
    for (int it = 0; it < 2; it++) {
        int idx = tid + it * 256;          // 0..511
        int r = idx >> 2, seg = idx & 3;   // row, 16B segment (8 bf16)
        const __nv_bfloat16* gp = g_xb + (size_t)(bm * 128 + r) * DIMK + k0 + seg * 8;
        cp_async16(a_base + (uint32_t)(r * AROW_U + seg * 4) * 4u, gp);
    }
    // B: 1024 x 16B chunks (4 floats each)
#pragma unroll
    for (int it = 0; it < 4; it++) {
        int idx = tid + it * 256;          // 0..1023
        int r = idx >> 3, seg = idx & 7;   // row, 16B segment (4 floats)
        const float* gp = Bv + (size_t)(bn * 128 + r) * DIMK + k0 + seg * 4;
        cp_async16(b_base + (uint32_t)(r * BROW_F + seg * 4) * 4u, gp);
    }
    cp_commit();
}

__global__ __launch_bounds__(256) void gemm_bf16(const float* __restrict__ Bv, int Brows) {
    extern __shared__ uint32_t sm[];
    const int bm = blockIdx.x, bn = blockIdx.y;   // bm fastest -> B-tile L2 reuse
    const int tid = threadIdx.x, lane = tid & 31, warp = tid >> 5;
    const int wm = warp >> 2, wn = warp & 3;      // 2 x 4 warp grid, warp tile 64x32
    const int g = lane >> 2, tg = lane & 3;

    uint32_t smb;
    asm("{ .reg .u64 t; cvta.to.shared.u64 t, %1; cvt.u32.u64 %0, t; }" : "=r"(smb) : "l"(sm));

    float acc[4][4][4];
#pragma unroll
    for (int i = 0; i < 4; i++)
#pragma unroll
        for (int j = 0; j < 4; j++)
#pragma unroll
            for (int r = 0; r < 4; r++) acc[i][j][r] = 0.f;

    gemm_load_stage(smb, 0, bm, bn, 0, Bv, tid);
    gemm_load_stage(smb, 1, bm, bn, 32, Bv, tid);

    for (int kt = 0; kt < NKSTEP; kt++) {
        if (kt >= NKSTEP - 2) cp_wait0(); else cp_wait1();
        __syncthreads();

        const uint32_t* As = sm + (kt % 3) * STAGE_U;
        const float*    Bs = (const float*)(As + A_STAGE_U);

#pragma unroll
        for (int ks = 0; ks < 2; ks++) {
            const int kbA = ks * 8;    // uint offset into A row (16 bf16)
            const int kbB = ks * 16;   // float offset into B row
            uint32_t af[4][4];
            uint32_t bf[4][2];
#pragma unroll
            for (int i = 0; i < 4; i++) {
                int r0 = wm * 64 + i * 16 + g;
                af[i][0] = As[r0 * AROW_U + kbA + tg];
                af[i][1] = As[(r0 + 8) * AROW_U + kbA + tg];
                af[i][2] = As[r0 * AROW_U + kbA + tg + 4];
                af[i][3] = As[(r0 + 8) * AROW_U + kbA + tg + 4];
            }
#pragma unroll
            for (int j = 0; j < 4; j++) {
                int n0 = wn * 32 + j * 8 + g;
                float2 p0 = *(const float2*)(Bs + n0 * BROW_F + kbB + 2 * tg);
                float2 p1 = *(const float2*)(Bs + n0 * BROW_F + kbB + 2 * tg + 8);
                bf[j][0] = cvt_bf16x2(p0.x, p0.y);
                bf[j][1] = cvt_bf16x2(p1.x, p1.y);
            }
#pragma unroll
            for (int i = 0; i < 4; i++)
#pragma unroll
                for (int j = 0; j < 4; j++) mma_bf16(acc[i][j], af[i], bf[j]);
        }

        if (kt + 2 < NKSTEP)
            gemm_load_stage(smb, (kt + 2) % 3, bm, bn, (kt + 2) * 32, Bv, tid);
    }

    // epilogue: c0,c1 = (row g, cols 2tg,2tg+1); c2,c3 = row g+8
#pragma unroll
    for (int i = 0; i < 4; i++) {
#pragma unroll
        for (int j = 0; j < 4; j++) {
            int row = bm * 128 + wm * 64 + i * 16 + g;
            int col = bn * 128 + wn * 32 + j * 8 + 2 * tg;
            if (row < Brows)
                *(float2*)(g_logits + (size_t)row * NTOT + col) =
                    make_float2(acc[i][j][0], acc[i][j][1]);
            if (row + 8 < Brows)
                *(float2*)(g_logits + (size_t)(row + 8) * NTOT + col) =
                    make_float2(acc[i][j][2], acc[i][j][3]);
        }
    }
}

// ---------------- kernel 3: per-row losses (one block per sample) ----------------
__global__ __launch_bounds__(256) void rowloss_kernel(const int* __restrict__ labels,
                                                      const int* __restrict__ cams) {
    extern __shared__ float srow[];        // NTOT floats (64 KB)
    __shared__ float scr[8];
    __shared__ float s_ori[CCAM];
    __shared__ unsigned hist[256];
    __shared__ unsigned sh_prefix;
    __shared__ int sh_need;

    const int b = blockIdx.x, tid = threadIdx.x;
    const int cam = cams[b], label = labels[b];
    const float invT = 1.0f / TEMP;
    const float* row = g_logits + (size_t)b * NTOT;

    for (int i = tid; i < NTOT; i += 256) srow[i] = row[i];
    __syncthreads();

    // intra-camera CE on own bank (unmasked)
    float mx = -1e30f;
    for (int i = tid; i < PBANK; i += 256) mx = fmaxf(mx, srow[cam * PBANK + i]);
    mx = block_max(mx, scr);
    float se = 0.f;
    for (int i = tid; i < PBANK; i += 256) se += expf((srow[cam * PBANK + i] - mx) * invT);
    se = block_sum(se, scr);
    const float ce = mx * invT + logf(se) - srow[cam * PBANK + label] * invT;

    // save positives, then mask them
    if (tid < CCAM) s_ori[tid] = srow[tid * PBANK + label];
    __syncthreads();
    if (tid < CCAM) srow[tid * PBANK + label] = -10000.0f;
    __syncthreads();

    // masked-row max + positives -> global stabilizer
    float m2 = -1e30f;
    for (int i = tid; i < NTOT; i += 256) m2 = fmaxf(m2, srow[i]);
    m2 = block_max(m2, scr);
    float M = m2;
#pragma unroll
    for (int c = 0; c < CCAM; c++) M = fmaxf(M, s_ori[c]);

    // exact top-K threshold via 4-pass 256-bin radix select
    unsigned prefix = 0;
    int need = KSEL;
    for (int p = 0; p < 4; p++) {
        const int shift = 24 - 8 * p;
        hist[tid] = 0u;
        __syncthreads();
        for (int i = tid; i < NTOT; i += 256) {
            unsigned key = fkey(srow[i]);
            bool ok = (p == 0) || ((key >> (shift + 8)) == (prefix >> (shift + 8)));
            unsigned bal = __ballot_sync(0xffffffffu, ok);
            if (ok) {
                unsigned bin = (key >> shift) & 0xFFu;
                unsigned mm = __match_any_sync(bal, bin);
                if ((int)(tid & 31) == __ffs(mm) - 1)
                    atomicAdd(&hist[bin], (unsigned)__popc(mm));
            }
        }
        __syncthreads();
        if (tid == 0) {
            int cum = 0, bsel = 0;
            for (int bb = 255; bb >= 0; --bb) {
                int h = (int)hist[bb];
                if (cum + h >= need) { bsel = bb; break; }
                cum += h;
            }
            sh_need = need - cum;
            sh_prefix = prefix | ((unsigned)bsel << shift);
        }
        __syncthreads();
        prefix = sh_prefix;
        need = sh_need;
        __syncthreads();
    }
    const float tval = funkey(prefix);

    // sum exp over top-K negatives (strict-greater + `need` copies of threshold)
    float local = 0.f;
    for (int i = tid; i < NTOT; i += 256) {
        float v = srow[i];
        if (fkey(v) > prefix) local += expf((v - M) * invT);
    }
    local = block_sum(local, scr);

    if (tid == 0) {
        float ssel = local + (float)need * expf((tval - M) * invT);
        float sori = 0.f, osum = 0.f;
#pragma unroll
        for (int c = 0; c < CCAM; c++) {
            sori += expf((s_ori[c] - M) * invT);
            osum += s_ori[c];
        }
        float lse = M * invT + logf(ssel + sori);
        g_lk[b] = lse - osum * invT * (1.0f / (float)CCAM);
        g_ce[b] = ce;
    }
}

// ---------------- kernel 4: per-camera means, warp-per-camera, deterministic ----------------
__global__ __launch_bounds__(256) void final_kernel(const int* __restrict__ cams,
                                                    float* __restrict__ out, int B) {
    __shared__ float s_i[CCAM], s_n[CCAM];
    const int w = threadIdx.x >> 5;
    const int l = threadIdx.x & 31;
    float se = 0.f, sl = 0.f, cn = 0.f;
    for (int b = l; b < B; b += 32) {
        if (cams[b] == w) { se += g_ce[b]; sl += g_lk[b]; cn += 1.f; }
    }
    se = warp_sum(se);
    sl = warp_sum(sl);
    cn = warp_sum(cn);
    if (l == 0) {
        s_i[w] = (cn > 0.f) ? se / cn : 0.f;
        s_n[w] = (cn > 0.f) ? sl / cn : 0.f;
    }
    __syncthreads();
    if (threadIdx.x == 0) {
        float a = 0.f, bsum = 0.f;
#pragma unroll
        for (int k = 0; k < CCAM; k++) { a += s_i[k]; bsum += s_n[k]; }
        out[0] = a;           // loss_intra
        out[1] = 0.5f * bsum; // loss_inter (LOSS_WEIGHT = 0.5)
    }
}

// ---------------- launch ----------------
extern "C" void kernel_launch(void* const* d_in, const int* in_sizes, int n_in,
                              void* d_out, int out_size) {
    const float* inputs = (const float*)d_in[0];
    const int*   labels = (const int*)d_in[1];
    const int*   cams   = (const int*)d_in[2];
    const float* tempV  = (const float*)d_in[3];
    const int B = in_sizes[1];  // labels element count

    prep_kernel<<<B, 256>>>(inputs);

    cudaFuncSetAttribute(gemm_bf16, cudaFuncAttributeMaxDynamicSharedMemorySize, GSMEM);
    dim3 grid((B + 127) / 128, NTOT / 128);   // bm fastest -> B-tile shared via L2
    gemm_bf16<<<grid, 256, GSMEM>>>(tempV, B);

    cudaFuncSetAttribute(rowloss_kernel, cudaFuncAttributeMaxDynamicSharedMemorySize,
                         NTOT * (int)sizeof(float));
    rowloss_kernel<<<B, 256, NTOT * sizeof(float)>>>(labels, cams);

    final_kernel<<<1, 256>>>(cams, (float*)d_out, B);
}